// round 12
// baseline (speedup 1.0000x reference)
#include <cuda_runtime.h>
#include <cuda_fp16.h>
#include <cstdint>
#include <cstddef>

#define DEV __device__ __forceinline__

// ============================================================================
// Device global scratch
// ============================================================================
// A fp16 activations, fragment-packed for mma.m16n8k16:
//   [mt(M/16)][kt16(128)][lane(32)] x uint4 (regs a0..a3)
__device__ __align__(256) __half g_A[(size_t)32768 * 2048];
// B ternary fp16 weights (quaternion signs folded), PAIR-packed:
//   [ntp(128)][kt16(128)][lane(32)] x uint4 {b0_even,b1_even,b0_odd,b1_odd}
__device__ __align__(256) __half g_B[(size_t)2048 * 2048];
__device__ float g_part[128][2];     // partial sums: [slice*4+w][{sum, abs}]
__device__ float g_outscale;

// ============================================================================
// PTX helpers
// ============================================================================
DEV uint32_t smem_u32(const void* p) {
    uint32_t a;
    asm("{ .reg .u64 t; cvta.to.shared.u64 t, %1; cvt.u32.u64 %0, t; }" : "=r"(a) : "l"(p));
    return a;
}
DEV void cp_async16(uint32_t dst, const void* src) {
    asm volatile("cp.async.cg.shared.global [%0], [%1], 16;" :: "r"(dst), "l"(src) : "memory");
}
DEV void cp_commit() { asm volatile("cp.async.commit_group;" ::: "memory"); }
template <int N> DEV void cp_wait() { asm volatile("cp.async.wait_group %0;" :: "n"(N) : "memory"); }

// mma.sync m16n8k16, fp16 x fp16 -> f32
DEV void mma_f16(float& d0, float& d1, float& d2, float& d3,
                 uint32_t a0, uint32_t a1, uint32_t a2, uint32_t a3,
                 uint32_t b0, uint32_t b1) {
    asm volatile(
        "mma.sync.aligned.m16n8k16.row.col.f32.f16.f16.f32 "
        "{%0,%1,%2,%3}, {%4,%5,%6,%7}, {%8,%9}, {%0,%1,%2,%3};"
        : "+f"(d0), "+f"(d1), "+f"(d2), "+f"(d3)
        : "r"(a0), "r"(a1), "r"(a2), "r"(a3), "r"(b0), "r"(b1));
}

DEV unsigned h2u(float a, float b) {
    __half2 h = __floats2half2_rn(a, b);
    return *reinterpret_cast<unsigned*>(&h);
}

// ============================================================================
// Quaternion block tables: t = (o>>9)*4 + (k>>9)
// ============================================================================
__device__ __constant__ int   c_sel[16] = {0,1,2,3,  1,0,3,2,  2,3,0,1,  3,2,1,0};
__device__ __constant__ float c_sgn[16] = {1.f,-1.f,-1.f,-1.f,  1.f,1.f,1.f,-1.f,
                                           1.f,-1.f,1.f,1.f,    1.f,1.f,-1.f,1.f};

// ============================================================================
// Kernel 1: partial per-weight mean / mean|w| (128 blocks = 4 weights x 32 slices)
// ============================================================================
__global__ void reduce_w_kernel(const float* __restrict__ rw, const float* __restrict__ iw,
                                const float* __restrict__ jw, const float* __restrict__ kw) {
    const float* ws[4] = {rw, iw, jw, kw};
    const int w     = blockIdx.x & 3;
    const int slice = blockIdx.x >> 2;
    const float4* w4 = (const float4*)ws[w] + (size_t)slice * 2048;
    float s = 0.f, sa = 0.f;
#pragma unroll
    for (int u = 0; u < 8; u++) {
        float4 v = w4[threadIdx.x + u * 256];
        s  += v.x + v.y + v.z + v.w;
        sa += fabsf(v.x) + fabsf(v.y) + fabsf(v.z) + fabsf(v.w);
    }
    __shared__ float sh[16];
    for (int o = 16; o; o >>= 1) {
        s  += __shfl_down_sync(0xFFFFFFFFu, s, o);
        sa += __shfl_down_sync(0xFFFFFFFFu, sa, o);
    }
    int wid = threadIdx.x >> 5, lane = threadIdx.x & 31;
    if (lane == 0) { sh[wid] = s; sh[wid + 8] = sa; }
    __syncthreads();
    if (threadIdx.x == 0) {
        float ts = 0.f, tsa = 0.f;
#pragma unroll
        for (int q = 0; q < 8; q++) { ts += sh[q]; tsa += sh[q + 8]; }
        g_part[blockIdx.x][0] = ts;
        g_part[blockIdx.x][1] = tsa;
    }
}

// ============================================================================
// Kernel 2 (FUSED): blocks [0,2048)            = pack_w (inline finalize)
//                   blocks [2048, 2048+MT*2)   = pack_x (smem-staged, k-half)
//   pack_w (LSU/L2-bound) overlaps pack_x (DRAM-bound).
//   NOTE: pack_w needs exactly 2048 blocks (128*128*32 threads / 256).
// ============================================================================
static constexpr int NPACKW = 2048;
static constexpr int PACKX_SMEM = 16 * 1032 * 2;   // 33024 B

__global__ void fused_pack_kernel(const float* __restrict__ x,
                                  const float* __restrict__ rw, const float* __restrict__ iw,
                                  const float* __restrict__ jw, const float* __restrict__ kw) {
    extern __shared__ __half sx[];                 // pack_x: [16][1032]; pack_w: 12 floats
    const int tid = threadIdx.x;

    if (blockIdx.x < NPACKW) {
        // ---- inline finalize: each block re-reduces g_part (L2-hot, 128 ld) ----
        float* sf = (float*)sx;                    // [0..3]=mean, [4..7]=inv, [8..11]=scale
        if (tid < 4) {
            float ts = 0.f, tsa = 0.f;
#pragma unroll
            for (int q = 0; q < 32; q++) {
                ts  += g_part[q * 4 + tid][0];
                tsa += g_part[q * 4 + tid][1];
            }
            float mean = ts / 262144.f;
            float sc   = fmaxf(tsa / 262144.f, 1e-8f);
            sf[tid]     = mean;
            sf[tid + 4] = 1.f / sc;
            sf[tid + 8] = sc;
        }
        __syncthreads();
        if (blockIdx.x == 0 && tid == 0)
            g_outscale = (sf[8] + sf[9] + sf[10] + sf[11]) * 0.125f;

        // ---- pack_w: PAIRED fp16 B-fragment layout (float2 loads) ----
        const float* ws[4] = {rw, iw, jw, kw};
        int t = blockIdx.x * 256 + tid;            // [0, 128*128*32)
        int lane = t & 31;
        int kt   = (t >> 5) & 127;
        int ntp  = t >> 12;
        int o0 = ntp * 16 + (lane >> 2);
        int o1 = o0 + 8;
        int k0 = kt * 16 + 2 * (lane & 3);

        auto qw2 = [&](int o, int kk) -> float2 {
            int tb = ((o >> 9) << 2) | (kk >> 9);
            int s  = c_sel[tb];
            float2 v = *(const float2*)(ws[s] + (size_t)(o & 511) * 512 + (kk & 511));
            float sg = c_sgn[tb], mean = sf[s], inv = sf[s + 4];
            float2 q;
            q.x = sg * rintf(fminf(fmaxf((v.x - mean) * inv, -1.f), 1.f));
            q.y = sg * rintf(fminf(fmaxf((v.y - mean) * inv, -1.f), 1.f));
            return q;
        };
        float2 q00 = qw2(o0, k0);
        float2 q01 = qw2(o0, k0 + 8);
        float2 q10 = qw2(o1, k0);
        float2 q11 = qw2(o1, k0 + 8);
        uint4 pk;
        pk.x = h2u(q00.x, q00.y);
        pk.y = h2u(q01.x, q01.y);
        pk.z = h2u(q10.x, q10.y);
        pk.w = h2u(q11.x, q11.y);
        ((uint4*)g_B)[t] = pk;
        return;
    }

    // ---- pack_x: 16 rows x 1024 cols per block ----
    const int bid  = blockIdx.x - NPACKW;
    const int mt   = bid >> 1;
    const int half = bid & 1;
    const float4* xr = (const float4*)(x + (size_t)mt * 16 * 2048) + half * 256;
#pragma unroll
    for (int u = 0; u < 16; u++) {
        int idx = tid + u * 256;                   // [0, 4096)
        int r  = idx >> 8;                         // 0..15
        int c4 = idx & 255;                        // float4 within 1024-col half
        float4 v = xr[(size_t)r * 512 + c4];
        uint2 h;
        h.x = h2u(v.x, v.y);
        h.y = h2u(v.z, v.w);
        *(uint2*)(sx + r * 1032 + c4 * 4) = h;
    }
    __syncthreads();
    uint4* A4 = (uint4*)g_A;
#pragma unroll
    for (int u = 0; u < 8; u++) {
        int idx  = tid + u * 256;                  // [0, 2048) = ktl*32 + lane
        int lane = idx & 31;
        int ktl  = idx >> 5;                       // 0..63 local kt16
        int r  = lane >> 2, c = lane & 3;
        int k0 = ktl * 16 + 2 * c;
        uint4 pk;
        pk.x = *(const uint32_t*)(sx + r * 1032 + k0);
        pk.y = *(const uint32_t*)(sx + (r + 8) * 1032 + k0);
        pk.z = *(const uint32_t*)(sx + r * 1032 + k0 + 8);
        pk.w = *(const uint32_t*)(sx + (r + 8) * 1032 + k0 + 8);
        A4[(size_t)mt * 4096 + (half * 64 + ktl) * 32 + lane] = pk;
    }
}

// ============================================================================
// Kernel 3: fp16 GEMM  out[M,2048] = (A @ W_big^T + bias) * osc
//   CTA tile 128x128, 4 warps (2m x 2n), warp tile 64x64.
//   K-tile 32 (2 x k16), 4-stage cp.async pipeline, ONE sync per iteration.
//   Issue order: ks0 frags -> next-stage cp.async -> MMA ks0 -> ks1 frags -> MMA ks1.
// ============================================================================
static constexpr int NS = 4;
static constexpr int STAGE_BYTES = 16384;             // A 8KB + B 8KB
static constexpr int GEMM_SMEM   = NS * STAGE_BYTES;  // 64 KB

__global__ void __launch_bounds__(128, 2)
quat_gemm_kernel(float* __restrict__ out, const float* __restrict__ bias, int MT) {
    extern __shared__ char smem[];
    const uint32_t smem_base = smem_u32(smem);
    const int tid    = threadIdx.x;
    const int lane   = tid & 31;
    const int wid    = tid >> 5;
    const int warp_m = wid & 1;           // 0..1
    const int warp_n = wid >> 1;          // 0..1
    const int mtile0 = blockIdx.y * 8;    // 8 m16-tiles per CTA
    const int ntp0   = blockIdx.x * 8;    // 8 n16-pairs per CTA

    const int NIT = 64;                   // K=2048 / 32

    float acc[4][8][4];
#pragma unroll
    for (int i = 0; i < 4; i++)
#pragma unroll
        for (int j = 0; j < 8; j++)
#pragma unroll
            for (int q = 0; q < 4; q++) acc[i][j][q] = 0.f;

    // Incrementally-bumped gmem cursors (k advances by 64 uint4 per iteration)
    const uint4* Acur = (const uint4*)g_A + ((size_t)mtile0 * 128) * 32 + (tid & 63);
    const uint4* Bcur = (const uint4*)g_B + ((size_t)ntp0   * 128) * 32 + (tid & 63);
    const int tl_a = tid >> 6;            // 0..1: covers tiles {tl, tl+2, tl+4, tl+6}

    auto issue_stage = [&](int s, const uint4* Ab, const uint4* Bb) {
        const uint32_t sA = smem_base + s * STAGE_BYTES;
        const uint32_t sB = sA + 8192;
#pragma unroll
        for (int u = 0; u < 4; u++) {
            int tl = tl_a + u * 2;              // tile-local 0..7
            cp_async16(sA + (tl * 64 + (tid & 63)) * 16, Ab + (size_t)tl * 4096);
            cp_async16(sB + (tl * 64 + (tid & 63)) * 16, Bb + (size_t)tl * 4096);
        }
        cp_commit();
    };

    auto do_mma = [&](const uint4* a, const uint4* bq) {
#pragma unroll
        for (int mtl = 0; mtl < 4; mtl++)
#pragma unroll
            for (int p = 0; p < 4; p++) {
                mma_f16(acc[mtl][2 * p][0], acc[mtl][2 * p][1],
                        acc[mtl][2 * p][2], acc[mtl][2 * p][3],
                        a[mtl].x, a[mtl].y, a[mtl].z, a[mtl].w,
                        bq[p].x, bq[p].y);
                mma_f16(acc[mtl][2 * p + 1][0], acc[mtl][2 * p + 1][1],
                        acc[mtl][2 * p + 1][2], acc[mtl][2 * p + 1][3],
                        a[mtl].x, a[mtl].y, a[mtl].z, a[mtl].w,
                        bq[p].z, bq[p].w);
            }
    };

    issue_stage(0, Acur,       Bcur);
    issue_stage(1, Acur + 64,  Bcur + 64);
    issue_stage(2, Acur + 128, Bcur + 128);
    Acur += 192; Bcur += 192;

#pragma unroll 1
    for (int i = 0; i < NIT; ++i) {
        cp_wait<2>();                           // stage i has landed
        __syncthreads();                        // all warps done reading stage i-1

        const int s = i & 3;
        const uint4* Asm = (const uint4*)(smem + s * STAGE_BYTES);
        const uint4* Bsm = (const uint4*)(smem + s * STAGE_BYTES + 8192);

        // ks = 0 fragments FIRST (tensor pipe starts ASAP after barrier)
        uint4 a0[4], b0[4];
#pragma unroll
        for (int mtl = 0; mtl < 4; mtl++)
            a0[mtl] = Asm[((warp_m * 4 + mtl) * 2 + 0) * 32 + lane];
#pragma unroll
        for (int p = 0; p < 4; p++)
            b0[p] = Bsm[((warp_n * 4 + p) * 2 + 0) * 32 + lane];

        // next stage's copies issue while MMA ks=0 runs
        if (i + 3 < NIT) {
            issue_stage((i + 3) & 3, Acur, Bcur);
            Acur += 64; Bcur += 64;
        } else {
            cp_commit();                        // keep group count uniform
        }

        do_mma(a0, b0);

        uint4 a1[4], b1[4];
#pragma unroll
        for (int mtl = 0; mtl < 4; mtl++)
            a1[mtl] = Asm[((warp_m * 4 + mtl) * 2 + 1) * 32 + lane];
#pragma unroll
        for (int p = 0; p < 4; p++)
            b1[p] = Bsm[((warp_n * 4 + p) * 2 + 1) * 32 + lane];

        do_mma(a1, b1);
    }

    // ---- epilogue: (acc + bias) * osc, direct float2 stores ----
    const float osc = g_outscale;
    const int r = lane >> 2, c = lane & 3;
    const int m_base = (mtile0 + warp_m * 4) * 16 + r;
    const int n_base = ntp0 * 16 + warp_n * 64 + 2 * c;
#pragma unroll
    for (int mtl = 0; mtl < 4; mtl++) {
        const int mrow = m_base + mtl * 16;
#pragma unroll
        for (int ntl = 0; ntl < 8; ntl++) {
            const int nc = n_base + ntl * 8;
            float2 bv = *(const float2*)(bias + nc);
            float2 o0, o1;
            o0.x = (acc[mtl][ntl][0] + bv.x) * osc;
            o0.y = (acc[mtl][ntl][1] + bv.y) * osc;
            o1.x = (acc[mtl][ntl][2] + bv.x) * osc;
            o1.y = (acc[mtl][ntl][3] + bv.y) * osc;
            *(float2*)(out + (size_t)mrow * 2048 + nc)       = o0;
            *(float2*)(out + (size_t)(mrow + 8) * 2048 + nc) = o1;
        }
    }
}

// ============================================================================
// Host launch — graph-capturable: kernel launches only
// ============================================================================
extern "C" void kernel_launch(void* const* d_in, const int* in_sizes, int n_in,
                              void* d_out, int out_size) {
    const float* x    = (const float*)d_in[0];
    const float* rw   = (const float*)d_in[1];
    const float* iw   = (const float*)d_in[2];
    const float* jw   = (const float*)d_in[3];
    const float* kw   = (const float*)d_in[4];
    const float* bias = (const float*)d_in[5];
    float* out = (float*)d_out;
    const int M  = in_sizes[0] / 2048;   // 16384
    const int MT = M / 16;

    reduce_w_kernel<<<128, 256>>>(rw, iw, jw, kw);

    cudaFuncSetAttribute(fused_pack_kernel,
                         cudaFuncAttributeMaxDynamicSharedMemorySize, PACKX_SMEM);
    fused_pack_kernel<<<NPACKW + MT * 2, 256, PACKX_SMEM>>>(x, rw, iw, jw, kw);

    cudaFuncSetAttribute(quat_gemm_kernel,
                         cudaFuncAttributeMaxDynamicSharedMemorySize, GEMM_SMEM);
    dim3 grid(2048 / 128, M / 128);      // x = n fastest (A-tile reuse in L2)
    quat_gemm_kernel<<<grid, 128, GEMM_SMEM>>>(out, bias, MT);
}

// round 13
// speedup vs baseline: 1.1514x; 1.1514x over previous
#include <cuda_runtime.h>
#include <cuda_fp16.h>
#include <cstdint>
#include <cstddef>

#define DEV __device__ __forceinline__

// ============================================================================
// Device global scratch
// ============================================================================
// A fp16 activations, fragment-packed for mma.m16n8k16:
//   [mt(M/16)][kt16(128)][lane(32)] x uint4 (regs a0..a3)
__device__ __align__(256) __half g_A[(size_t)32768 * 2048];
// B ternary fp16 weights (quaternion signs folded), PAIR-packed:
//   [ntp(128)][kt16(128)][lane(32)] x uint4 {b0_even,b1_even,b0_odd,b1_odd}
__device__ __align__(256) __half g_B[(size_t)2048 * 2048];
__device__ float g_part[128][2];     // partial sums: [slice*4+w][{sum, abs}]
__device__ float g_outscale;

// ============================================================================
// PTX helpers
// ============================================================================
DEV uint32_t smem_u32(const void* p) {
    uint32_t a;
    asm("{ .reg .u64 t; cvta.to.shared.u64 t, %1; cvt.u32.u64 %0, t; }" : "=r"(a) : "l"(p));
    return a;
}
DEV void cp_async16(uint32_t dst, const void* src) {
    asm volatile("cp.async.cg.shared.global [%0], [%1], 16;" :: "r"(dst), "l"(src) : "memory");
}
DEV void cp_commit() { asm volatile("cp.async.commit_group;" ::: "memory"); }
template <int N> DEV void cp_wait() { asm volatile("cp.async.wait_group %0;" :: "n"(N) : "memory"); }

// mma.sync m16n8k16, fp16 x fp16 -> f32
DEV void mma_f16(float& d0, float& d1, float& d2, float& d3,
                 uint32_t a0, uint32_t a1, uint32_t a2, uint32_t a3,
                 uint32_t b0, uint32_t b1) {
    asm volatile(
        "mma.sync.aligned.m16n8k16.row.col.f32.f16.f16.f32 "
        "{%0,%1,%2,%3}, {%4,%5,%6,%7}, {%8,%9}, {%0,%1,%2,%3};"
        : "+f"(d0), "+f"(d1), "+f"(d2), "+f"(d3)
        : "r"(a0), "r"(a1), "r"(a2), "r"(a3), "r"(b0), "r"(b1));
}

DEV unsigned h2u(float a, float b) {
    __half2 h = __floats2half2_rn(a, b);
    return *reinterpret_cast<unsigned*>(&h);
}

// ============================================================================
// Quaternion block tables: t = (o>>9)*4 + (k>>9)
// ============================================================================
__device__ __constant__ int   c_sel[16] = {0,1,2,3,  1,0,3,2,  2,3,0,1,  3,2,1,0};
__device__ __constant__ float c_sgn[16] = {1.f,-1.f,-1.f,-1.f,  1.f,1.f,1.f,-1.f,
                                           1.f,-1.f,1.f,1.f,    1.f,1.f,-1.f,1.f};

// ============================================================================
// Kernel 1: partial per-weight mean / mean|w| (128 blocks = 4 weights x 32 slices)
// ============================================================================
__global__ void reduce_w_kernel(const float* __restrict__ rw, const float* __restrict__ iw,
                                const float* __restrict__ jw, const float* __restrict__ kw) {
    const float* ws[4] = {rw, iw, jw, kw};
    const int w     = blockIdx.x & 3;
    const int slice = blockIdx.x >> 2;
    const float4* w4 = (const float4*)ws[w] + (size_t)slice * 2048;
    float s = 0.f, sa = 0.f;
#pragma unroll
    for (int u = 0; u < 8; u++) {
        float4 v = w4[threadIdx.x + u * 256];
        s  += v.x + v.y + v.z + v.w;
        sa += fabsf(v.x) + fabsf(v.y) + fabsf(v.z) + fabsf(v.w);
    }
    __shared__ float sh[16];
    for (int o = 16; o; o >>= 1) {
        s  += __shfl_down_sync(0xFFFFFFFFu, s, o);
        sa += __shfl_down_sync(0xFFFFFFFFu, sa, o);
    }
    int wid = threadIdx.x >> 5, lane = threadIdx.x & 31;
    if (lane == 0) { sh[wid] = s; sh[wid + 8] = sa; }
    __syncthreads();
    if (threadIdx.x == 0) {
        float ts = 0.f, tsa = 0.f;
#pragma unroll
        for (int q = 0; q < 8; q++) { ts += sh[q]; tsa += sh[q + 8]; }
        g_part[blockIdx.x][0] = ts;
        g_part[blockIdx.x][1] = tsa;
    }
}

// ============================================================================
// Kernel 2 (FUSED): blocks [0,2048)            = pack_w (inline finalize)
//                   blocks [2048, 2048+MT*2)   = pack_x (smem-staged, k-half)
//   pack_w (LSU/L2-bound) overlaps pack_x (DRAM-bound).
// ============================================================================
static constexpr int NPACKW = 2048;
static constexpr int PACKX_SMEM = 16 * 1032 * 2;   // 33024 B

__global__ void fused_pack_kernel(const float* __restrict__ x,
                                  const float* __restrict__ rw, const float* __restrict__ iw,
                                  const float* __restrict__ jw, const float* __restrict__ kw) {
    extern __shared__ __half sx[];                 // pack_x: [16][1032]; pack_w: 12 floats
    const int tid = threadIdx.x;

    if (blockIdx.x < NPACKW) {
        // ---- inline finalize: each block re-reduces g_part (L2-hot, 128 ld) ----
        float* sf = (float*)sx;                    // [0..3]=mean, [4..7]=inv, [8..11]=scale
        if (tid < 4) {
            float ts = 0.f, tsa = 0.f;
#pragma unroll
            for (int q = 0; q < 32; q++) {
                ts  += g_part[q * 4 + tid][0];
                tsa += g_part[q * 4 + tid][1];
            }
            float mean = ts / 262144.f;
            float sc   = fmaxf(tsa / 262144.f, 1e-8f);
            sf[tid]     = mean;
            sf[tid + 4] = 1.f / sc;
            sf[tid + 8] = sc;
        }
        __syncthreads();
        if (blockIdx.x == 0 && tid == 0)
            g_outscale = (sf[8] + sf[9] + sf[10] + sf[11]) * 0.125f;

        // ---- pack_w: PAIRED fp16 B-fragment layout (float2 loads) ----
        const float* ws[4] = {rw, iw, jw, kw};
        int t = blockIdx.x * 256 + tid;            // [0, 128*128*32)
        int lane = t & 31;
        int kt   = (t >> 5) & 127;
        int ntp  = t >> 12;
        int o0 = ntp * 16 + (lane >> 2);
        int o1 = o0 + 8;
        int k0 = kt * 16 + 2 * (lane & 3);

        auto qw2 = [&](int o, int kk) -> float2 {
            int tb = ((o >> 9) << 2) | (kk >> 9);
            int s  = c_sel[tb];
            float2 v = *(const float2*)(ws[s] + (size_t)(o & 511) * 512 + (kk & 511));
            float sg = c_sgn[tb], mean = sf[s], inv = sf[s + 4];
            float2 q;
            q.x = sg * rintf(fminf(fmaxf((v.x - mean) * inv, -1.f), 1.f));
            q.y = sg * rintf(fminf(fmaxf((v.y - mean) * inv, -1.f), 1.f));
            return q;
        };
        float2 q00 = qw2(o0, k0);
        float2 q01 = qw2(o0, k0 + 8);
        float2 q10 = qw2(o1, k0);
        float2 q11 = qw2(o1, k0 + 8);
        uint4 pk;
        pk.x = h2u(q00.x, q00.y);
        pk.y = h2u(q01.x, q01.y);
        pk.z = h2u(q10.x, q10.y);
        pk.w = h2u(q11.x, q11.y);
        ((uint4*)g_B)[t] = pk;
        return;
    }

    // ---- pack_x: 16 rows x 1024 cols per block ----
    const int bid  = blockIdx.x - NPACKW;
    const int mt   = bid >> 1;
    const int half = bid & 1;
    const float4* xr = (const float4*)(x + (size_t)mt * 16 * 2048) + half * 256;
#pragma unroll
    for (int u = 0; u < 16; u++) {
        int idx = tid + u * 256;                   // [0, 4096)
        int r  = idx >> 8;                         // 0..15
        int c4 = idx & 255;                        // float4 within 1024-col half
        float4 v = xr[(size_t)r * 512 + c4];
        uint2 h;
        h.x = h2u(v.x, v.y);
        h.y = h2u(v.z, v.w);
        *(uint2*)(sx + r * 1032 + c4 * 4) = h;
    }
    __syncthreads();
    uint4* A4 = (uint4*)g_A;
#pragma unroll
    for (int u = 0; u < 8; u++) {
        int idx  = tid + u * 256;                  // [0, 2048) = ktl*32 + lane
        int lane = idx & 31;
        int ktl  = idx >> 5;                       // 0..63 local kt16
        int r  = lane >> 2, c = lane & 3;
        int k0 = ktl * 16 + 2 * c;
        uint4 pk;
        pk.x = *(const uint32_t*)(sx + r * 1032 + k0);
        pk.y = *(const uint32_t*)(sx + (r + 8) * 1032 + k0);
        pk.z = *(const uint32_t*)(sx + r * 1032 + k0 + 8);
        pk.w = *(const uint32_t*)(sx + (r + 8) * 1032 + k0 + 8);
        A4[(size_t)mt * 4096 + (half * 64 + ktl) * 32 + lane] = pk;
    }
}

// ============================================================================
// Kernel 3: fp16 GEMM  out[M,2048] = (A @ W_big^T + bias) * osc
//   CTA tile 128x128, 4 warps (2m x 2n), warp tile 64x64.
//   K-tile 32 (2 x k16), 4-stage cp.async pipeline, ONE sync per iteration.
//   EXACT R10 structure (fragments loaded per-ks inside the loop; no extra
//   live registers across issue_stage -> no spills; 230 regs).
// ============================================================================
static constexpr int NS = 4;
static constexpr int STAGE_BYTES = 16384;             // A 8KB + B 8KB
static constexpr int GEMM_SMEM   = NS * STAGE_BYTES;  // 64 KB

__global__ void __launch_bounds__(128, 2)
quat_gemm_kernel(float* __restrict__ out, const float* __restrict__ bias, int MT) {
    extern __shared__ char smem[];
    const uint32_t smem_base = smem_u32(smem);
    const int tid    = threadIdx.x;
    const int lane   = tid & 31;
    const int wid    = tid >> 5;
    const int warp_m = wid & 1;           // 0..1
    const int warp_n = wid >> 1;          // 0..1
    const int mtile0 = blockIdx.y * 8;    // 8 m16-tiles per CTA
    const int ntp0   = blockIdx.x * 8;    // 8 n16-pairs per CTA

    const int NIT = 64;                   // K=2048 / 32

    float acc[4][8][4];
#pragma unroll
    for (int i = 0; i < 4; i++)
#pragma unroll
        for (int j = 0; j < 8; j++)
#pragma unroll
            for (int q = 0; q < 4; q++) acc[i][j][q] = 0.f;

    // Incrementally-bumped gmem cursors (k advances by 64 uint4 per iteration)
    const uint4* Acur = (const uint4*)g_A + ((size_t)mtile0 * 128) * 32 + (tid & 63);
    const uint4* Bcur = (const uint4*)g_B + ((size_t)ntp0   * 128) * 32 + (tid & 63);
    const int tl_a = tid >> 6;            // 0..1: covers tiles {tl, tl+2, tl+4, tl+6}

    auto issue_stage = [&](int s, const uint4* Ab, const uint4* Bb) {
        const uint32_t sA = smem_base + s * STAGE_BYTES;
        const uint32_t sB = sA + 8192;
#pragma unroll
        for (int u = 0; u < 4; u++) {
            int tl = tl_a + u * 2;              // tile-local 0..7
            cp_async16(sA + (tl * 64 + (tid & 63)) * 16, Ab + (size_t)tl * 4096);
            cp_async16(sB + (tl * 64 + (tid & 63)) * 16, Bb + (size_t)tl * 4096);
        }
        cp_commit();
    };

    issue_stage(0, Acur,       Bcur);
    issue_stage(1, Acur + 64,  Bcur + 64);
    issue_stage(2, Acur + 128, Bcur + 128);
    Acur += 192; Bcur += 192;

#pragma unroll 1
    for (int i = 0; i < NIT; ++i) {
        cp_wait<2>();                           // stage i has landed
        __syncthreads();                        // all warps done reading stage i-1
        if (i + 3 < NIT) {
            issue_stage((i + 3) & 3, Acur, Bcur);
            Acur += 64; Bcur += 64;
        } else {
            cp_commit();                        // keep group count uniform
        }

        const int s = i & 3;
        const uint4* Asm = (const uint4*)(smem + s * STAGE_BYTES);
        const uint4* Bsm = (const uint4*)(smem + s * STAGE_BYTES + 8192);
#pragma unroll
        for (int ks = 0; ks < 2; ks++) {
            uint4 a[4];
            uint4 bq[4];
#pragma unroll
            for (int mtl = 0; mtl < 4; mtl++)
                a[mtl] = Asm[((warp_m * 4 + mtl) * 2 + ks) * 32 + lane];
#pragma unroll
            for (int p = 0; p < 4; p++)
                bq[p] = Bsm[((warp_n * 4 + p) * 2 + ks) * 32 + lane];
#pragma unroll
            for (int mtl = 0; mtl < 4; mtl++)
#pragma unroll
                for (int p = 0; p < 4; p++) {
                    mma_f16(acc[mtl][2 * p][0], acc[mtl][2 * p][1],
                            acc[mtl][2 * p][2], acc[mtl][2 * p][3],
                            a[mtl].x, a[mtl].y, a[mtl].z, a[mtl].w,
                            bq[p].x, bq[p].y);
                    mma_f16(acc[mtl][2 * p + 1][0], acc[mtl][2 * p + 1][1],
                            acc[mtl][2 * p + 1][2], acc[mtl][2 * p + 1][3],
                            a[mtl].x, a[mtl].y, a[mtl].z, a[mtl].w,
                            bq[p].z, bq[p].w);
                }
        }
    }

    // ---- epilogue: (acc + bias) * osc, direct float2 stores ----
    const float osc = g_outscale;
    const int r = lane >> 2, c = lane & 3;
    const int m_base = (mtile0 + warp_m * 4) * 16 + r;
    const int n_base = ntp0 * 16 + warp_n * 64 + 2 * c;
#pragma unroll
    for (int mtl = 0; mtl < 4; mtl++) {
        const int mrow = m_base + mtl * 16;
#pragma unroll
        for (int ntl = 0; ntl < 8; ntl++) {
            const int nc = n_base + ntl * 8;
            float2 bv = *(const float2*)(bias + nc);
            float2 o0, o1;
            o0.x = (acc[mtl][ntl][0] + bv.x) * osc;
            o0.y = (acc[mtl][ntl][1] + bv.y) * osc;
            o1.x = (acc[mtl][ntl][2] + bv.x) * osc;
            o1.y = (acc[mtl][ntl][3] + bv.y) * osc;
            *(float2*)(out + (size_t)mrow * 2048 + nc)       = o0;
            *(float2*)(out + (size_t)(mrow + 8) * 2048 + nc) = o1;
        }
    }
}

// ============================================================================
// Host launch — graph-capturable: kernel launches only
// ============================================================================
extern "C" void kernel_launch(void* const* d_in, const int* in_sizes, int n_in,
                              void* d_out, int out_size) {
    const float* x    = (const float*)d_in[0];
    const float* rw   = (const float*)d_in[1];
    const float* iw   = (const float*)d_in[2];
    const float* jw   = (const float*)d_in[3];
    const float* kw   = (const float*)d_in[4];
    const float* bias = (const float*)d_in[5];
    float* out = (float*)d_out;
    const int M  = in_sizes[0] / 2048;   // 16384
    const int MT = M / 16;

    reduce_w_kernel<<<128, 256>>>(rw, iw, jw, kw);

    cudaFuncSetAttribute(fused_pack_kernel,
                         cudaFuncAttributeMaxDynamicSharedMemorySize, PACKX_SMEM);
    fused_pack_kernel<<<NPACKW + MT * 2, 256, PACKX_SMEM>>>(x, rw, iw, jw, kw);

    cudaFuncSetAttribute(quat_gemm_kernel,
                         cudaFuncAttributeMaxDynamicSharedMemorySize, GEMM_SMEM);
    dim3 grid(2048 / 128, M / 128);      // x = n fastest (A-tile reuse in L2)
    quat_gemm_kernel<<<grid, 128, GEMM_SMEM>>>(out, bias, MT);
}

// round 14
// speedup vs baseline: 1.1549x; 1.0031x over previous
#include <cuda_runtime.h>
#include <cuda_fp16.h>
#include <cstdint>
#include <cstddef>

#define DEV __device__ __forceinline__

// ============================================================================
// Device global scratch
// ============================================================================
// A fp16 activations, fragment-packed for mma.m16n8k16:
//   [mt(M/16)][kt16(128)][lane(32)] x uint4 (regs a0..a3)
__device__ __align__(256) __half g_A[(size_t)32768 * 2048];
// B ternary fp16 weights (quaternion signs folded), PAIR-packed:
//   [ntp(128)][kt16(128)][lane(32)] x uint4 {b0_even,b1_even,b0_odd,b1_odd}
__device__ __align__(256) __half g_B[(size_t)2048 * 2048];
__device__ float g_part[512][2];     // partials: [w*128 + slice][{sum, abs}]
__device__ float g_outscale;

// ============================================================================
// PTX helpers
// ============================================================================
DEV uint32_t smem_u32(const void* p) {
    uint32_t a;
    asm("{ .reg .u64 t; cvta.to.shared.u64 t, %1; cvt.u32.u64 %0, t; }" : "=r"(a) : "l"(p));
    return a;
}
// NOTE: no "memory" clobber — lets ptxas hoist (independent-stage) smem LDS
// above the copy issues. Ordering vs commit/wait holds because volatile asms
// are never reordered among themselves; LDS ordering vs stage reuse is fenced
// by cp_wait/__syncthreads which DO carry clobbers.
DEV void cp_async16(uint32_t dst, const void* src) {
    asm volatile("cp.async.cg.shared.global [%0], [%1], 16;" :: "r"(dst), "l"(src));
}
DEV void cp_commit() { asm volatile("cp.async.commit_group;" ::: "memory"); }
template <int N> DEV void cp_wait() { asm volatile("cp.async.wait_group %0;" :: "n"(N) : "memory"); }

// mma.sync m16n8k16, fp16 x fp16 -> f32
DEV void mma_f16(float& d0, float& d1, float& d2, float& d3,
                 uint32_t a0, uint32_t a1, uint32_t a2, uint32_t a3,
                 uint32_t b0, uint32_t b1) {
    asm volatile(
        "mma.sync.aligned.m16n8k16.row.col.f32.f16.f16.f32 "
        "{%0,%1,%2,%3}, {%4,%5,%6,%7}, {%8,%9}, {%0,%1,%2,%3};"
        : "+f"(d0), "+f"(d1), "+f"(d2), "+f"(d3)
        : "r"(a0), "r"(a1), "r"(a2), "r"(a3), "r"(b0), "r"(b1));
}

DEV unsigned h2u(float a, float b) {
    __half2 h = __floats2half2_rn(a, b);
    return *reinterpret_cast<unsigned*>(&h);
}

// ============================================================================
// Quaternion block tables: t = (o>>9)*4 + (k>>9)
// ============================================================================
__device__ __constant__ int   c_sel[16] = {0,1,2,3,  1,0,3,2,  2,3,0,1,  3,2,1,0};
__device__ __constant__ float c_sgn[16] = {1.f,-1.f,-1.f,-1.f,  1.f,1.f,1.f,-1.f,
                                           1.f,-1.f,1.f,1.f,    1.f,1.f,-1.f,1.f};

// ============================================================================
// Kernel 1: partial per-weight mean / mean|w|
//   512 blocks = 4 weights x 128 slices (4x the MLP of the 128-block version)
// ============================================================================
__global__ void reduce_w_kernel(const float* __restrict__ rw, const float* __restrict__ iw,
                                const float* __restrict__ jw, const float* __restrict__ kw) {
    const float* ws[4] = {rw, iw, jw, kw};
    const int w     = blockIdx.x >> 7;         // 0..3
    const int slice = blockIdx.x & 127;        // 0..127
    const float4* w4 = (const float4*)ws[w] + (size_t)slice * 512;
    float4 v0 = w4[threadIdx.x];
    float4 v1 = w4[threadIdx.x + 256];
    float s  = v0.x + v0.y + v0.z + v0.w + v1.x + v1.y + v1.z + v1.w;
    float sa = fabsf(v0.x) + fabsf(v0.y) + fabsf(v0.z) + fabsf(v0.w)
             + fabsf(v1.x) + fabsf(v1.y) + fabsf(v1.z) + fabsf(v1.w);
    __shared__ float sh[16];
    for (int o = 16; o; o >>= 1) {
        s  += __shfl_down_sync(0xFFFFFFFFu, s, o);
        sa += __shfl_down_sync(0xFFFFFFFFu, sa, o);
    }
    int wid = threadIdx.x >> 5, lane = threadIdx.x & 31;
    if (lane == 0) { sh[wid] = s; sh[wid + 8] = sa; }
    __syncthreads();
    if (threadIdx.x == 0) {
        float ts = 0.f, tsa = 0.f;
#pragma unroll
        for (int q = 0; q < 8; q++) { ts += sh[q]; tsa += sh[q + 8]; }
        g_part[blockIdx.x][0] = ts;
        g_part[blockIdx.x][1] = tsa;
    }
}

// ============================================================================
// Kernel 2 (FUSED): blocks [0,2048)            = pack_w (inline finalize)
//                   blocks [2048, 2048+MT*2)   = pack_x (smem-staged, k-half)
//   pack_w (LSU/L2-bound) overlaps pack_x (DRAM-bound).
// ============================================================================
static constexpr int NPACKW = 2048;
static constexpr int PACKX_SMEM = 16 * 1032 * 2;   // 33024 B

__global__ void fused_pack_kernel(const float* __restrict__ x,
                                  const float* __restrict__ rw, const float* __restrict__ iw,
                                  const float* __restrict__ jw, const float* __restrict__ kw) {
    extern __shared__ __half sx[];                 // pack_x: [16][1032]; pack_w: 12 floats
    const int tid = threadIdx.x;

    if (blockIdx.x < NPACKW) {
        // ---- inline finalize: warp w (w<4) shuffle-reduces its 128 partials ----
        float* sf = (float*)sx;                    // [0..3]=mean, [4..7]=inv, [8..11]=scale
        const int wid  = tid >> 5;
        const int lane = tid & 31;
        if (wid < 4) {
            float ts = 0.f, tsa = 0.f;
#pragma unroll
            for (int q = 0; q < 4; q++) {          // 4 entries per lane (L2-hot)
                ts  += g_part[wid * 128 + q * 32 + lane][0];
                tsa += g_part[wid * 128 + q * 32 + lane][1];
            }
            for (int o = 16; o; o >>= 1) {
                ts  += __shfl_down_sync(0xFFFFFFFFu, ts, o);
                tsa += __shfl_down_sync(0xFFFFFFFFu, tsa, o);
            }
            if (lane == 0) {
                float mean = ts / 262144.f;
                float sc   = fmaxf(tsa / 262144.f, 1e-8f);
                sf[wid]     = mean;
                sf[wid + 4] = 1.f / sc;
                sf[wid + 8] = sc;
            }
        }
        __syncthreads();
        if (blockIdx.x == 0 && tid == 0)
            g_outscale = (sf[8] + sf[9] + sf[10] + sf[11]) * 0.125f;

        // ---- pack_w: PAIRED fp16 B-fragment layout (float2 loads) ----
        const float* ws[4] = {rw, iw, jw, kw};
        int t = blockIdx.x * 256 + tid;            // [0, 128*128*32)
        int lane2 = t & 31;
        int kt   = (t >> 5) & 127;
        int ntp  = t >> 12;
        int o0 = ntp * 16 + (lane2 >> 2);
        int o1 = o0 + 8;
        int k0 = kt * 16 + 2 * (lane2 & 3);

        auto qw2 = [&](int o, int kk) -> float2 {
            int tb = ((o >> 9) << 2) | (kk >> 9);
            int s  = c_sel[tb];
            float2 v = *(const float2*)(ws[s] + (size_t)(o & 511) * 512 + (kk & 511));
            float sg = c_sgn[tb], mean = sf[s], inv = sf[s + 4];
            float2 q;
            q.x = sg * rintf(fminf(fmaxf((v.x - mean) * inv, -1.f), 1.f));
            q.y = sg * rintf(fminf(fmaxf((v.y - mean) * inv, -1.f), 1.f));
            return q;
        };
        float2 q00 = qw2(o0, k0);
        float2 q01 = qw2(o0, k0 + 8);
        float2 q10 = qw2(o1, k0);
        float2 q11 = qw2(o1, k0 + 8);
        uint4 pk;
        pk.x = h2u(q00.x, q00.y);
        pk.y = h2u(q01.x, q01.y);
        pk.z = h2u(q10.x, q10.y);
        pk.w = h2u(q11.x, q11.y);
        ((uint4*)g_B)[t] = pk;
        return;
    }

    // ---- pack_x: 16 rows x 1024 cols per block ----
    const int bid  = blockIdx.x - NPACKW;
    const int mt   = bid >> 1;
    const int half = bid & 1;
    const float4* xr = (const float4*)(x + (size_t)mt * 16 * 2048) + half * 256;
#pragma unroll
    for (int u = 0; u < 16; u++) {
        int idx = tid + u * 256;                   // [0, 4096)
        int r  = idx >> 8;                         // 0..15
        int c4 = idx & 255;                        // float4 within 1024-col half
        float4 v = xr[(size_t)r * 512 + c4];
        uint2 h;
        h.x = h2u(v.x, v.y);
        h.y = h2u(v.z, v.w);
        *(uint2*)(sx + r * 1032 + c4 * 4) = h;
    }
    __syncthreads();
    uint4* A4 = (uint4*)g_A;
#pragma unroll
    for (int u = 0; u < 8; u++) {
        int idx  = tid + u * 256;                  // [0, 2048) = ktl*32 + lane
        int lane = idx & 31;
        int ktl  = idx >> 5;                       // 0..63 local kt16
        int r  = lane >> 2, c = lane & 3;
        int k0 = ktl * 16 + 2 * c;
        uint4 pk;
        pk.x = *(const uint32_t*)(sx + r * 1032 + k0);
        pk.y = *(const uint32_t*)(sx + (r + 8) * 1032 + k0);
        pk.z = *(const uint32_t*)(sx + r * 1032 + k0 + 8);
        pk.w = *(const uint32_t*)(sx + (r + 8) * 1032 + k0 + 8);
        A4[(size_t)mt * 4096 + (half * 64 + ktl) * 32 + lane] = pk;
    }
}

// ============================================================================
// Kernel 3: fp16 GEMM  out[M,2048] = (A @ W_big^T + bias) * osc
//   CTA tile 128x128, 4 warps (2m x 2n), warp tile 64x64.
//   K-tile 32 (2 x k16), 4-stage cp.async pipeline, ONE sync per iteration.
//   R13 structure; only change: cp.async asm has no "memory" clobber so the
//   fragment LDS can be scheduled before/among the copy issues.
// ============================================================================
static constexpr int NS = 4;
static constexpr int STAGE_BYTES = 16384;             // A 8KB + B 8KB
static constexpr int GEMM_SMEM   = NS * STAGE_BYTES;  // 64 KB

__global__ void __launch_bounds__(128, 2)
quat_gemm_kernel(float* __restrict__ out, const float* __restrict__ bias, int MT) {
    extern __shared__ char smem[];
    const uint32_t smem_base = smem_u32(smem);
    const int tid    = threadIdx.x;
    const int lane   = tid & 31;
    const int wid    = tid >> 5;
    const int warp_m = wid & 1;           // 0..1
    const int warp_n = wid >> 1;          // 0..1
    const int mtile0 = blockIdx.y * 8;    // 8 m16-tiles per CTA
    const int ntp0   = blockIdx.x * 8;    // 8 n16-pairs per CTA

    const int NIT = 64;                   // K=2048 / 32

    float acc[4][8][4];
#pragma unroll
    for (int i = 0; i < 4; i++)
#pragma unroll
        for (int j = 0; j < 8; j++)
#pragma unroll
            for (int q = 0; q < 4; q++) acc[i][j][q] = 0.f;

    // Incrementally-bumped gmem cursors (k advances by 64 uint4 per iteration)
    const uint4* Acur = (const uint4*)g_A + ((size_t)mtile0 * 128) * 32 + (tid & 63);
    const uint4* Bcur = (const uint4*)g_B + ((size_t)ntp0   * 128) * 32 + (tid & 63);
    const int tl_a = tid >> 6;            // 0..1: covers tiles {tl, tl+2, tl+4, tl+6}

    auto issue_stage = [&](int s, const uint4* Ab, const uint4* Bb) {
        const uint32_t sA = smem_base + s * STAGE_BYTES;
        const uint32_t sB = sA + 8192;
#pragma unroll
        for (int u = 0; u < 4; u++) {
            int tl = tl_a + u * 2;              // tile-local 0..7
            cp_async16(sA + (tl * 64 + (tid & 63)) * 16, Ab + (size_t)tl * 4096);
            cp_async16(sB + (tl * 64 + (tid & 63)) * 16, Bb + (size_t)tl * 4096);
        }
        cp_commit();
    };

    issue_stage(0, Acur,       Bcur);
    issue_stage(1, Acur + 64,  Bcur + 64);
    issue_stage(2, Acur + 128, Bcur + 128);
    Acur += 192; Bcur += 192;

#pragma unroll 1
    for (int i = 0; i < NIT; ++i) {
        cp_wait<2>();                           // stage i has landed
        __syncthreads();                        // all warps done reading stage i-1
        if (i + 3 < NIT) {
            issue_stage((i + 3) & 3, Acur, Bcur);
            Acur += 64; Bcur += 64;
        } else {
            cp_commit();                        // keep group count uniform
        }

        const int s = i & 3;
        const uint4* Asm = (const uint4*)(smem + s * STAGE_BYTES);
        const uint4* Bsm = (const uint4*)(smem + s * STAGE_BYTES + 8192);
#pragma unroll
        for (int ks = 0; ks < 2; ks++) {
            uint4 a[4];
            uint4 bq[4];
#pragma unroll
            for (int mtl = 0; mtl < 4; mtl++)
                a[mtl] = Asm[((warp_m * 4 + mtl) * 2 + ks) * 32 + lane];
#pragma unroll
            for (int p = 0; p < 4; p++)
                bq[p] = Bsm[((warp_n * 4 + p) * 2 + ks) * 32 + lane];
#pragma unroll
            for (int mtl = 0; mtl < 4; mtl++)
#pragma unroll
                for (int p = 0; p < 4; p++) {
                    mma_f16(acc[mtl][2 * p][0], acc[mtl][2 * p][1],
                            acc[mtl][2 * p][2], acc[mtl][2 * p][3],
                            a[mtl].x, a[mtl].y, a[mtl].z, a[mtl].w,
                            bq[p].x, bq[p].y);
                    mma_f16(acc[mtl][2 * p + 1][0], acc[mtl][2 * p + 1][1],
                            acc[mtl][2 * p + 1][2], acc[mtl][2 * p + 1][3],
                            a[mtl].x, a[mtl].y, a[mtl].z, a[mtl].w,
                            bq[p].z, bq[p].w);
                }
        }
    }

    // ---- epilogue: (acc + bias) * osc, direct float2 stores ----
    const float osc = g_outscale;
    const int r = lane >> 2, c = lane & 3;
    const int m_base = (mtile0 + warp_m * 4) * 16 + r;
    const int n_base = ntp0 * 16 + warp_n * 64 + 2 * c;
#pragma unroll
    for (int mtl = 0; mtl < 4; mtl++) {
        const int mrow = m_base + mtl * 16;
#pragma unroll
        for (int ntl = 0; ntl < 8; ntl++) {
            const int nc = n_base + ntl * 8;
            float2 bv = *(const float2*)(bias + nc);
            float2 o0, o1;
            o0.x = (acc[mtl][ntl][0] + bv.x) * osc;
            o0.y = (acc[mtl][ntl][1] + bv.y) * osc;
            o1.x = (acc[mtl][ntl][2] + bv.x) * osc;
            o1.y = (acc[mtl][ntl][3] + bv.y) * osc;
            *(float2*)(out + (size_t)mrow * 2048 + nc)       = o0;
            *(float2*)(out + (size_t)(mrow + 8) * 2048 + nc) = o1;
        }
    }
}

// ============================================================================
// Host launch — graph-capturable: kernel launches only
// ============================================================================
extern "C" void kernel_launch(void* const* d_in, const int* in_sizes, int n_in,
                              void* d_out, int out_size) {
    const float* x    = (const float*)d_in[0];
    const float* rw   = (const float*)d_in[1];
    const float* iw   = (const float*)d_in[2];
    const float* jw   = (const float*)d_in[3];
    const float* kw   = (const float*)d_in[4];
    const float* bias = (const float*)d_in[5];
    float* out = (float*)d_out;
    const int M  = in_sizes[0] / 2048;   // 16384
    const int MT = M / 16;

    reduce_w_kernel<<<512, 256>>>(rw, iw, jw, kw);

    cudaFuncSetAttribute(fused_pack_kernel,
                         cudaFuncAttributeMaxDynamicSharedMemorySize, PACKX_SMEM);
    fused_pack_kernel<<<NPACKW + MT * 2, 256, PACKX_SMEM>>>(x, rw, iw, jw, kw);

    cudaFuncSetAttribute(quat_gemm_kernel,
                         cudaFuncAttributeMaxDynamicSharedMemorySize, GEMM_SMEM);
    dim3 grid(2048 / 128, M / 128);      // x = n fastest (A-tile reuse in L2)
    quat_gemm_kernel<<<grid, 128, GEMM_SMEM>>>(out, bias, MT);
}